// round 15
// baseline (speedup 1.0000x reference)
#include <cuda_runtime.h>
#include <cuda_bf16.h>
#include <cuda_fp16.h>
#include <math.h>
#include <stdint.h>

#define NLVL 16
#define NDENSE 5
#define NHASH (NLVL - NDENSE)
#define TBLSZ (1u << 19)
#define HMASK (TBLSZ - 1u)
#define FSCALE 8192.0f
#define INV_FSCALE (1.0f / 8192.0f)
#define PY 2654435761u
#define PZ 805459861u
#define HASH_QUADS (NHASH * TBLSZ / 4)   // 1441792
#define DENSE_CELLS 532784

// dynamic smem layout
#define SM_W1_BYTES   (128 * 80)          // 10240
#define SM_ENC_BYTES  (256 * 80)          // 20480 per buffer
#define SM_TOTAL      (SM_W1_BYTES + 2 * SM_ENC_BYTES)   // 51200

typedef unsigned long long ull;

struct LvlParams {
    float scale[NLVL];
    int   res[NLVL];
    int   denseBase[NDENSE];
};

// W1 combined+transposed bf16 [128 hidden][32 feat], scaled 1/FSCALE
__device__ __align__(16) unsigned short g_w1tb[128 * 32];
// layer-2 weights: [0:64) dw2, [64:128) fw2 col0, [128:192) col1, [192:256) col2
__device__ __align__(16) float g_w2[256];
// fp8 (e4m3) hash table for levels 5..15 (scaled x8192)
__device__ __align__(16) unsigned short g_hash8[NHASH * TBLSZ];
// fp8 duplicated-corner dense records, levels 0..4
__device__ __align__(16) uint4 g_dense8[DENSE_CELLS];

// ---------------- helpers ----------------
__device__ __forceinline__ uint32_t smem_u32(const void* p) {
    uint32_t a;
    asm("{ .reg .u64 t; cvta.to.shared.u64 t, %1; cvt.u32.u64 %0, t; }" : "=r"(a) : "l"(p));
    return a;
}
__device__ __forceinline__ unsigned short f8pack(float f0, float f1) {
    unsigned short r;
    asm("cvt.rn.satfinite.e4m3x2.f32 %0, %1, %2;" : "=h"(r) : "f"(f1), "f"(f0));
    return r;
}
__device__ __forceinline__ __half2 f8unpack(unsigned short u) {
    unsigned r;
    asm("cvt.rn.f16x2.e4m3x2 %0, %1;" : "=r"(r) : "h"(u));
    return *reinterpret_cast<__half2*>(&r);
}
__device__ __forceinline__ unsigned bf16x2_of(float lo, float hi) {
    unsigned r;
    asm("cvt.rn.bf16x2.f32 %0, %1, %2;" : "=r"(r) : "f"(hi), "f"(lo));
    return r;
}
__device__ __forceinline__ void ldsm_x4(uint32_t addr, uint32_t& r0, uint32_t& r1,
                                        uint32_t& r2, uint32_t& r3) {
    asm volatile("ldmatrix.sync.aligned.m8n8.x4.shared.b16 {%0,%1,%2,%3}, [%4];"
                 : "=r"(r0), "=r"(r1), "=r"(r2), "=r"(r3) : "r"(addr));
}
__device__ __forceinline__ void mma_bf16(float& d0, float& d1, float& d2, float& d3,
                                         uint32_t a0, uint32_t a1, uint32_t a2, uint32_t a3,
                                         uint32_t b0, uint32_t b1) {
    asm volatile(
        "mma.sync.aligned.m16n8k16.row.col.f32.bf16.bf16.f32 "
        "{%0,%1,%2,%3}, {%4,%5,%6,%7}, {%8,%9}, {%0,%1,%2,%3};"
        : "+f"(d0), "+f"(d1), "+f"(d2), "+f"(d3)
        : "r"(a0), "r"(a1), "r"(a2), "r"(a3), "r"(b0), "r"(b1));
}

// ---------------- single merged prologue kernel ----------------
__global__ void prep_all_kernel(const float* __restrict__ table,
                                const float* __restrict__ dw1,
                                const float* __restrict__ fw1,
                                const float* __restrict__ dw2,
                                const float* __restrict__ fw2,
                                LvlParams P)
{
    int t = blockIdx.x * 256 + threadIdx.x;

    if (t < HASH_QUADS) {
        const float4* src = reinterpret_cast<const float4*>(table)
                          + (size_t)NDENSE * (TBLSZ / 2) + (size_t)t * 2;
        float4 a = src[0];
        float4 b = src[1];
        uint2 o;
        o.x = (unsigned)f8pack(a.x * FSCALE, a.y * FSCALE)
            | ((unsigned)f8pack(a.z * FSCALE, a.w * FSCALE) << 16);
        o.y = (unsigned)f8pack(b.x * FSCALE, b.y * FSCALE)
            | ((unsigned)f8pack(b.z * FSCALE, b.w * FSCALE) << 16);
        reinterpret_cast<uint2*>(g_hash8)[t] = o;
    }

    if (t < DENSE_CELLS) {
        int l = 0;
        #pragma unroll
        for (int k = 1; k < NDENSE; k++)
            if (t >= P.denseBase[k]) l = k;
        int cid = t - P.denseBase[l];
        int R = P.res[l];
        int cx = cid % R;
        int u  = cid / R;
        int cy = u % R;
        int cz = u / R;
        const float2* tl = reinterpret_cast<const float2*>(table) + (size_t)l * TBLSZ;
        unsigned short e[8];
        #pragma unroll
        for (int c = 0; c < 8; c++) {
            int gx = min(cx + ((c >> 2) & 1), R - 1);
            int gy = min(cy + ((c >> 1) & 1), R - 1);
            int gz = min(cz + (c & 1), R - 1);
            float2 v = tl[gx + R * (gy + R * gz)];
            e[c] = f8pack(v.x * FSCALE, v.y * FSCALE);
        }
        uint4 o;
        o.x = (unsigned)e[0] | ((unsigned)e[1] << 16);
        o.y = (unsigned)e[2] | ((unsigned)e[3] << 16);
        o.z = (unsigned)e[4] | ((unsigned)e[5] << 16);
        o.w = (unsigned)e[6] | ((unsigned)e[7] << 16);
        g_dense8[t] = o;
    }

    if (t < 4096) {
        int j = t >> 5, k = t & 31;
        float v = (j < 64 ? dw1[k * 64 + j] : fw1[k * 64 + (j - 64)]) * INV_FSCALE;
        g_w1tb[t] = __bfloat16_as_ushort(__float2bfloat16(v));
    }

    if (t < 64) {
        g_w2[t]       = dw2[t];
        g_w2[64 + t]  = fw2[3 * t + 0];
        g_w2[128 + t] = fw2[3 * t + 1];
        g_w2[192 + t] = fw2[3 * t + 2];
    }
}

// ---------------- main kernel: persistent CTAs, double-buffered enc ----------------
__global__ void __launch_bounds__(256, 4)
nerf_field_kernel(const float* __restrict__ points,
                  float* __restrict__ out,
                  int N, int ntiles, LvlParams P)
{
    extern __shared__ __align__(16) unsigned char smem[];
    unsigned char* s_w1  = smem;                      // 128 x 80B
    unsigned char* s_enc = smem + SM_W1_BYTES;        // 2 x (256 x 80B)

    const int tid  = threadIdx.x;
    const int lane = tid & 31;
    const int warp = tid >> 5;
    const int g = lane >> 2;
    const int q = lane & 3;

    // stage W1 once per persistent block
    if (tid < 128) {
        const uint4* src = reinterpret_cast<const uint4*>(g_w1tb) + tid * 4;
        uint4* dst = reinterpret_cast<uint4*>(s_w1 + tid * 80);
        dst[0] = src[0]; dst[1] = src[1]; dst[2] = src[2]; dst[3] = src[3];
    }
    __syncthreads();

    const uint32_t swb = smem_u32(s_w1);
    const uint32_t senc0 = smem_u32(s_enc);

    int buf = 0;
    for (int tile = blockIdx.x; tile < ntiles; tile += gridDim.x, buf ^= 1) {
        unsigned char* encb = s_enc + buf * SM_ENC_BYTES;
        unsigned char* myrow = encb + tid * 80;

        int gid = tile * 256 + tid;
        int gc = min(gid, N - 1);

        float x = fminf(fmaxf((points[gc * 3 + 0] + 1.0f) * 0.5f, 0.0f), 1.0f);
        float y = fminf(fmaxf((points[gc * 3 + 1] + 1.0f) * 0.5f, 0.0f), 1.0f);
        float z = fminf(fmaxf((points[gc * 3 + 2] + 1.0f) * 0.5f, 0.0f), 1.0f);

        unsigned ew[4];   // 4 levels buffered -> one STS.128 per group

        // ---- dense levels 0..4 ----
        #pragma unroll
        for (int l = 0; l < NDENSE; l++) {
            const float sc = P.scale[l];
            const int   R  = P.res[l];
            float px = x * sc + 0.5f, py = y * sc + 0.5f, pz = z * sc + 0.5f;
            float fx = floorf(px), fy = floorf(py), fz = floorf(pz);
            float wx = px - fx,    wy = py - fy,    wz = pz - fz;
            int cell = (int)fx + R * ((int)fy + R * (int)fz);

            uint4 qd = __ldg(&g_dense8[P.denseBase[l] + cell]);

            float wx0 = 1.0f - wx, wy0 = 1.0f - wy, wz0 = 1.0f - wz;
            float w00 = wy0 * wz0, w01 = wy0 * wz, w10 = wy * wz0, w11 = wy * wz;

            __half2 a0 = __float2half2_rn(0.0f);
            __half2 a1 = __float2half2_rn(0.0f);
            a0 = __hfma2(__float2half2_rn(wx0 * w00), f8unpack((unsigned short)(qd.x      )), a0);
            a1 = __hfma2(__float2half2_rn(wx0 * w01), f8unpack((unsigned short)(qd.x >> 16)), a1);
            a0 = __hfma2(__float2half2_rn(wx0 * w10), f8unpack((unsigned short)(qd.y      )), a0);
            a1 = __hfma2(__float2half2_rn(wx0 * w11), f8unpack((unsigned short)(qd.y >> 16)), a1);
            a0 = __hfma2(__float2half2_rn(wx  * w00), f8unpack((unsigned short)(qd.z      )), a0);
            a1 = __hfma2(__float2half2_rn(wx  * w01), f8unpack((unsigned short)(qd.z >> 16)), a1);
            a0 = __hfma2(__float2half2_rn(wx  * w10), f8unpack((unsigned short)(qd.w      )), a0);
            a1 = __hfma2(__float2half2_rn(wx  * w11), f8unpack((unsigned short)(qd.w >> 16)), a1);
            float2 e = __half22float2(__hadd2(a0, a1));
            ew[l & 3] = bf16x2_of(e.x, e.y);
            if ((l & 3) == 3)
                *reinterpret_cast<uint4*>(myrow + (l >> 2) * 16) =
                    make_uint4(ew[0], ew[1], ew[2], ew[3]);
        }

        // ---- hashed levels 5..15 ----
        #pragma unroll
        for (int l = NDENSE; l < NLVL; l++) {
            const float sc = P.scale[l];
            const int   R  = P.res[l];
            float px = x * sc + 0.5f, py = y * sc + 0.5f, pz = z * sc + 0.5f;
            float fx = floorf(px), fy = floorf(py), fz = floorf(pz);
            float wx = px - fx,    wy = py - fy,    wz = pz - fz;
            int ix = (int)fx, iy = (int)fy, iz = (int)fz;

            unsigned x0 = (unsigned)ix;
            unsigned x1 = (ix + 1 < R) ? x0 + 1u : x0;
            unsigned hy0 = (unsigned)iy * PY;
            unsigned hy1 = (iy + 1 < R) ? hy0 + PY : hy0;
            unsigned hz0 = (unsigned)iz * PZ;
            unsigned hz1 = (iz + 1 < R) ? hz0 + PZ : hz0;

            const uint2* t8 = reinterpret_cast<const uint2*>(g_hash8)
                            + (size_t)(l - NDENSE) * (TBLSZ / 4);
            const unsigned* t4 = reinterpret_cast<const unsigned*>(g_hash8)
                               + (size_t)(l - NDENSE) * (TBLSZ / 2);

            float wwy[2] = {1.0f - wy, wy};
            float wwz[2] = {1.0f - wz, wz};
            unsigned hyv[2] = {hy0, hy1};
            unsigned hzv[2] = {hz0, hz1};
            float wA = 1.0f - wx, wB = wx;
            __half2 accA = __float2half2_rn(0.0f);
            __half2 accB = __float2half2_rn(0.0f);

            #pragma unroll
            for (int yi = 0; yi < 2; yi++) {
                #pragma unroll
                for (int zi = 0; zi < 2; zi++) {
                    unsigned h  = hyv[yi] ^ hzv[zi];
                    unsigned iA = (h ^ x0) & HMASK;
                    unsigned iB = (h ^ x1) & HMASK;
                    unsigned bA = iA >> 2;
                    uint2 qh = __ldg(t8 + bA);
                    unsigned wordA = (iA & 2) ? qh.y : qh.x;
                    unsigned short hwA = (unsigned short)(wordA >> ((iA & 1) << 4));
                    unsigned wordB;
                    if ((iB >> 2) == bA) {
                        wordB = (iB & 2) ? qh.y : qh.x;
                    } else {
                        wordB = __ldg(t4 + (iB >> 1));   // ~25% of lanes
                    }
                    unsigned short hwB = (unsigned short)(wordB >> ((iB & 1) << 4));

                    float wyz = wwy[yi] * wwz[zi];
                    accA = __hfma2(__float2half2_rn(wyz * wA), f8unpack(hwA), accA);
                    accB = __hfma2(__float2half2_rn(wyz * wB), f8unpack(hwB), accB);
                }
            }
            float2 e = __half22float2(__hadd2(accA, accB));
            ew[l & 3] = bf16x2_of(e.x, e.y);
            if ((l & 3) == 3)
                *reinterpret_cast<uint4*>(myrow + (l >> 2) * 16) =
                    make_uint4(ew[0], ew[1], ew[2], ew[3]);
        }

        __syncwarp();

        // ---- A fragments: 2 M-tiles x 2 K-tiles ----
        uint32_t sab = senc0 + buf * SM_ENC_BYTES + (warp * 32) * 80;
        uint32_t af[2][2][4];
        #pragma unroll
        for (int m = 0; m < 2; m++) {
            #pragma unroll
            for (int k = 0; k < 2; k++) {
                uint32_t addr = sab + (m * 16 + (lane & 15)) * 80 + k * 32 + ((lane >> 4) << 4);
                ldsm_x4(addr, af[m][k][0], af[m][k][1], af[m][k][2], af[m][k][3]);
            }
        }

        // ---- MMA over 16 n8-tiles, fused ReLU + layer-2 ----
        float dacc[4] = {0, 0, 0, 0};
        float c0[4] = {0, 0, 0, 0}, c1[4] = {0, 0, 0, 0}, c2[4] = {0, 0, 0, 0};

        #pragma unroll
        for (int n = 0; n < 16; n++) {
            uint32_t b0, b1, b2, b3;
            uint32_t baddr = swb + (8 * n + (lane & 7)) * 80 + ((lane >> 3) << 4);
            ldsm_x4(baddr, b0, b1, b2, b3);

            #pragma unroll
            for (int m = 0; m < 2; m++) {
                float d0 = 0, d1 = 0, d2 = 0, d3 = 0;
                mma_bf16(d0, d1, d2, d3,
                         af[m][0][0], af[m][0][1], af[m][0][2], af[m][0][3], b0, b1);
                mma_bf16(d0, d1, d2, d3,
                         af[m][1][0], af[m][1][1], af[m][1][2], af[m][1][3], b2, b3);
                float r0 = fmaxf(d0, 0.0f), r1 = fmaxf(d1, 0.0f);
                float r2 = fmaxf(d2, 0.0f), r3 = fmaxf(d3, 0.0f);
                if (n < 8) {
                    int j0 = 8 * n + 2 * q;
                    float w0 = __ldg(&g_w2[j0]), w1 = __ldg(&g_w2[j0 + 1]);
                    dacc[2 * m + 0] += r0 * w0 + r1 * w1;
                    dacc[2 * m + 1] += r2 * w0 + r3 * w1;
                } else {
                    int j0 = 8 * (n - 8) + 2 * q;
                    float wa0 = __ldg(&g_w2[64 + j0]),  wa1 = __ldg(&g_w2[64 + j0 + 1]);
                    float wb0 = __ldg(&g_w2[128 + j0]), wb1 = __ldg(&g_w2[128 + j0 + 1]);
                    float wc0 = __ldg(&g_w2[192 + j0]), wc1 = __ldg(&g_w2[192 + j0 + 1]);
                    c0[2 * m + 0] += r0 * wa0 + r1 * wa1;
                    c0[2 * m + 1] += r2 * wa0 + r3 * wa1;
                    c1[2 * m + 0] += r0 * wb0 + r1 * wb1;
                    c1[2 * m + 1] += r2 * wb0 + r3 * wb1;
                    c2[2 * m + 0] += r0 * wc0 + r1 * wc1;
                    c2[2 * m + 1] += r2 * wc0 + r3 * wc1;
                }
            }
        }

        #pragma unroll
        for (int i = 0; i < 4; i++) {
            dacc[i] += __shfl_xor_sync(0xFFFFFFFF, dacc[i], 1);
            dacc[i] += __shfl_xor_sync(0xFFFFFFFF, dacc[i], 2);
            c0[i]   += __shfl_xor_sync(0xFFFFFFFF, c0[i], 1);
            c0[i]   += __shfl_xor_sync(0xFFFFFFFF, c0[i], 2);
            c1[i]   += __shfl_xor_sync(0xFFFFFFFF, c1[i], 1);
            c1[i]   += __shfl_xor_sync(0xFFFFFFFF, c1[i], 2);
            c2[i]   += __shfl_xor_sync(0xFFFFFFFF, c2[i], 1);
            c2[i]   += __shfl_xor_sync(0xFFFFFFFF, c2[i], 2);
        }

        if (q == 0) {
            int base = tile * 256 + warp * 32;
            #pragma unroll
            for (int i = 0; i < 4; i++) {
                int pt = base + g + 16 * (i >> 1) + 8 * (i & 1);
                if (pt < N) {
                    float density = fmaxf(dacc[i], 0.0f) + log1pf(expf(-fabsf(dacc[i])));
                    out[pt * 3 + 0] = 1.0f / (1.0f + expf(-c0[i]));
                    out[pt * 3 + 1] = 1.0f / (1.0f + expf(-c1[i]));
                    out[pt * 3 + 2] = 1.0f / (1.0f + expf(-c2[i]));
                    out[(size_t)3 * N + pt] = density;
                }
            }
        }
    }
}

extern "C" void kernel_launch(void* const* d_in, const int* in_sizes, int n_in,
                              void* d_out, int out_size)
{
    const float* points = (const float*)d_in[0];
    const float* table  = (const float*)d_in[1];
    const float* dw1    = (const float*)d_in[2];
    const float* dw2    = (const float*)d_in[3];
    const float* fw1    = (const float*)d_in[4];
    const float* fw2    = (const float*)d_in[5];
    int N = in_sizes[0] / 3;

    LvlParams P;
    int cellBase = 0;
    for (int l = 0; l < NLVL; l++) {
        double sc = 16.0 * pow(1.447269237440378, (double)l) - 1.0;
        int res = (int)ceil(sc) + 1;
        P.scale[l] = (float)sc;
        P.res[l] = res;
        if (l < NDENSE) { P.denseBase[l] = cellBase; cellBase += res * res * res; }
    }

    static bool attr_set = false;
    if (!attr_set) {
        cudaFuncSetAttribute(nerf_field_kernel,
                             cudaFuncAttributeMaxDynamicSharedMemorySize, SM_TOTAL);
        attr_set = true;
    }

    // single merged prologue launch
    prep_all_kernel<<<(HASH_QUADS + 255) / 256, 256>>>(table, dw1, fw1, dw2, fw2, P);

    int ntiles = (N + 255) / 256;
    int blocks = 148 * 4;
    if (blocks > ntiles) blocks = ntiles;
    nerf_field_kernel<<<blocks, 256, SM_TOTAL>>>(points, (float*)d_out, N, ntiles, P);
}

// round 16
// speedup vs baseline: 2.0394x; 2.0394x over previous
#include <cuda_runtime.h>
#include <cuda_bf16.h>
#include <cuda_fp16.h>
#include <math.h>
#include <stdint.h>

#define NLVL 16
#define NDENSE 5
#define NHASH (NLVL - NDENSE)
#define TBLSZ (1u << 19)
#define HMASK (TBLSZ - 1u)
#define FSCALE 8192.0f
#define INV_FSCALE (1.0f / 8192.0f)
#define PY 2654435761u
#define PZ 805459861u
#define HASH_QUADS (NHASH * TBLSZ / 4)   // 1441792
#define DENSE_CELLS 532784

typedef unsigned long long ull;

struct LvlParams {
    float scale[NLVL];
    int   res[NLVL];
    int   denseBase[NDENSE];
};

// W1 combined+transposed bf16 [128 hidden][32 feat], scaled 1/FSCALE
__device__ __align__(16) unsigned short g_w1tb[128 * 32];
// layer-2 weights: [0:64) dw2, [64:128) fw2 col0, [128:192) col1, [192:256) col2
__device__ __align__(16) float g_w2[256];
// fp8 (e4m3) hash table for levels 5..15 (scaled x8192)
__device__ __align__(16) unsigned short g_hash8[NHASH * TBLSZ];
// fp8 duplicated-corner dense records, levels 0..4
__device__ __align__(16) uint4 g_dense8[DENSE_CELLS];

// ---------------- helpers ----------------
__device__ __forceinline__ uint32_t smem_u32(const void* p) {
    uint32_t a;
    asm("{ .reg .u64 t; cvta.to.shared.u64 t, %1; cvt.u32.u64 %0, t; }" : "=r"(a) : "l"(p));
    return a;
}
__device__ __forceinline__ unsigned short f8pack(float f0, float f1) {
    unsigned short r;
    asm("cvt.rn.satfinite.e4m3x2.f32 %0, %1, %2;" : "=h"(r) : "f"(f1), "f"(f0));
    return r;
}
__device__ __forceinline__ __half2 f8unpack(unsigned short u) {
    unsigned r;
    asm("cvt.rn.f16x2.e4m3x2 %0, %1;" : "=r"(r) : "h"(u));
    return *reinterpret_cast<__half2*>(&r);
}
__device__ __forceinline__ unsigned bf16x2_of(float lo, float hi) {
    unsigned r;
    asm("cvt.rn.bf16x2.f32 %0, %1, %2;" : "=r"(r) : "f"(hi), "f"(lo));
    return r;
}
__device__ __forceinline__ void ldsm_x4(uint32_t addr, uint32_t& r0, uint32_t& r1,
                                        uint32_t& r2, uint32_t& r3) {
    asm volatile("ldmatrix.sync.aligned.m8n8.x4.shared.b16 {%0,%1,%2,%3}, [%4];"
                 : "=r"(r0), "=r"(r1), "=r"(r2), "=r"(r3) : "r"(addr));
}
__device__ __forceinline__ void mma_bf16(float& d0, float& d1, float& d2, float& d3,
                                         uint32_t a0, uint32_t a1, uint32_t a2, uint32_t a3,
                                         uint32_t b0, uint32_t b1) {
    asm volatile(
        "mma.sync.aligned.m16n8k16.row.col.f32.bf16.bf16.f32 "
        "{%0,%1,%2,%3}, {%4,%5,%6,%7}, {%8,%9}, {%0,%1,%2,%3};"
        : "+f"(d0), "+f"(d1), "+f"(d2), "+f"(d3)
        : "r"(a0), "r"(a1), "r"(a2), "r"(a3), "r"(b0), "r"(b1));
}

// ---------------- single merged prologue kernel ----------------
__global__ void prep_all_kernel(const float* __restrict__ table,
                                const float* __restrict__ dw1,
                                const float* __restrict__ fw1,
                                const float* __restrict__ dw2,
                                const float* __restrict__ fw2,
                                LvlParams P)
{
    int t = blockIdx.x * 256 + threadIdx.x;

    if (t < HASH_QUADS) {
        const float4* src = reinterpret_cast<const float4*>(table)
                          + (size_t)NDENSE * (TBLSZ / 2) + (size_t)t * 2;
        float4 a = src[0];
        float4 b = src[1];
        uint2 o;
        o.x = (unsigned)f8pack(a.x * FSCALE, a.y * FSCALE)
            | ((unsigned)f8pack(a.z * FSCALE, a.w * FSCALE) << 16);
        o.y = (unsigned)f8pack(b.x * FSCALE, b.y * FSCALE)
            | ((unsigned)f8pack(b.z * FSCALE, b.w * FSCALE) << 16);
        reinterpret_cast<uint2*>(g_hash8)[t] = o;
    }

    if (t < DENSE_CELLS) {
        int l = 0;
        #pragma unroll
        for (int k = 1; k < NDENSE; k++)
            if (t >= P.denseBase[k]) l = k;
        int cid = t - P.denseBase[l];
        int R = P.res[l];
        int cx = cid % R;
        int u  = cid / R;
        int cy = u % R;
        int cz = u / R;
        const float2* tl = reinterpret_cast<const float2*>(table) + (size_t)l * TBLSZ;
        unsigned short e[8];
        #pragma unroll
        for (int c = 0; c < 8; c++) {
            int gx = min(cx + ((c >> 2) & 1), R - 1);
            int gy = min(cy + ((c >> 1) & 1), R - 1);
            int gz = min(cz + (c & 1), R - 1);
            float2 v = tl[gx + R * (gy + R * gz)];
            e[c] = f8pack(v.x * FSCALE, v.y * FSCALE);
        }
        uint4 o;
        o.x = (unsigned)e[0] | ((unsigned)e[1] << 16);
        o.y = (unsigned)e[2] | ((unsigned)e[3] << 16);
        o.z = (unsigned)e[4] | ((unsigned)e[5] << 16);
        o.w = (unsigned)e[6] | ((unsigned)e[7] << 16);
        g_dense8[t] = o;
    }

    if (t < 4096) {
        int j = t >> 5, k = t & 31;
        float v = (j < 64 ? dw1[k * 64 + j] : fw1[k * 64 + (j - 64)]) * INV_FSCALE;
        g_w1tb[t] = __bfloat16_as_ushort(__float2bfloat16(v));
    }

    if (t < 64) {
        g_w2[t]       = dw2[t];
        g_w2[64 + t]  = fw2[3 * t + 0];
        g_w2[128 + t] = fw2[3 * t + 1];
        g_w2[192 + t] = fw2[3 * t + 2];
    }
}

// ---------------- main kernel (R14 core: flat grid, 64 regs, occ 4) ----------------
__global__ void __launch_bounds__(256, 4)
nerf_field_kernel(const float* __restrict__ points,
                  float* __restrict__ out,
                  int N, LvlParams P)
{
    // stride 80B: 16B-aligned rows; STS.128 phases are bank-disjoint
    __shared__ __align__(16) unsigned char s_w1[128 * 80];
    __shared__ __align__(16) unsigned char s_enc[256 * 80];

    const int tid  = threadIdx.x;
    const int lane = tid & 31;
    const int warp = tid >> 5;
    const int g = lane >> 2;
    const int q = lane & 3;

    if (tid < 128) {
        const uint4* src = reinterpret_cast<const uint4*>(g_w1tb) + tid * 4;
        uint4* dst = reinterpret_cast<uint4*>(s_w1 + tid * 80);
        dst[0] = src[0]; dst[1] = src[1]; dst[2] = src[2]; dst[3] = src[3];
    }
    __syncthreads();

    int gid = blockIdx.x * 256 + tid;
    int gc = min(gid, N - 1);

    float x = fminf(fmaxf((points[gc * 3 + 0] + 1.0f) * 0.5f, 0.0f), 1.0f);
    float y = fminf(fmaxf((points[gc * 3 + 1] + 1.0f) * 0.5f, 0.0f), 1.0f);
    float z = fminf(fmaxf((points[gc * 3 + 2] + 1.0f) * 0.5f, 0.0f), 1.0f);

    unsigned char* myrow = s_enc + tid * 80;
    unsigned ew[4];   // 4 levels buffered -> one STS.128 per group

    // ---- dense levels 0..4 ----
    #pragma unroll
    for (int l = 0; l < NDENSE; l++) {
        const float sc = P.scale[l];
        const int   R  = P.res[l];
        float px = x * sc + 0.5f, py = y * sc + 0.5f, pz = z * sc + 0.5f;
        float fx = floorf(px), fy = floorf(py), fz = floorf(pz);
        float wx = px - fx,    wy = py - fy,    wz = pz - fz;
        int cell = (int)fx + R * ((int)fy + R * (int)fz);

        uint4 qd = __ldg(&g_dense8[P.denseBase[l] + cell]);

        float wx0 = 1.0f - wx, wy0 = 1.0f - wy, wz0 = 1.0f - wz;
        float w00 = wy0 * wz0, w01 = wy0 * wz, w10 = wy * wz0, w11 = wy * wz;

        __half2 a0 = __float2half2_rn(0.0f);
        __half2 a1 = __float2half2_rn(0.0f);
        a0 = __hfma2(__float2half2_rn(wx0 * w00), f8unpack((unsigned short)(qd.x      )), a0);
        a1 = __hfma2(__float2half2_rn(wx0 * w01), f8unpack((unsigned short)(qd.x >> 16)), a1);
        a0 = __hfma2(__float2half2_rn(wx0 * w10), f8unpack((unsigned short)(qd.y      )), a0);
        a1 = __hfma2(__float2half2_rn(wx0 * w11), f8unpack((unsigned short)(qd.y >> 16)), a1);
        a0 = __hfma2(__float2half2_rn(wx  * w00), f8unpack((unsigned short)(qd.z      )), a0);
        a1 = __hfma2(__float2half2_rn(wx  * w01), f8unpack((unsigned short)(qd.z >> 16)), a1);
        a0 = __hfma2(__float2half2_rn(wx  * w10), f8unpack((unsigned short)(qd.w      )), a0);
        a1 = __hfma2(__float2half2_rn(wx  * w11), f8unpack((unsigned short)(qd.w >> 16)), a1);
        float2 e = __half22float2(__hadd2(a0, a1));
        ew[l & 3] = bf16x2_of(e.x, e.y);
        if ((l & 3) == 3)
            *reinterpret_cast<uint4*>(myrow + (l >> 2) * 16) =
                make_uint4(ew[0], ew[1], ew[2], ew[3]);
    }

    // ---- hashed levels 5..15: 8B blocks; neighbor hashes via conditional IADD ----
    #pragma unroll
    for (int l = NDENSE; l < NLVL; l++) {
        const float sc = P.scale[l];
        const int   R  = P.res[l];
        float px = x * sc + 0.5f, py = y * sc + 0.5f, pz = z * sc + 0.5f;
        float fx = floorf(px), fy = floorf(py), fz = floorf(pz);
        float wx = px - fx,    wy = py - fy,    wz = pz - fz;
        int ix = (int)fx, iy = (int)fy, iz = (int)fz;

        unsigned x0 = (unsigned)ix;
        unsigned x1 = (ix + 1 < R) ? x0 + 1u : x0;
        unsigned hy0 = (unsigned)iy * PY;
        unsigned hy1 = (iy + 1 < R) ? hy0 + PY : hy0;
        unsigned hz0 = (unsigned)iz * PZ;
        unsigned hz1 = (iz + 1 < R) ? hz0 + PZ : hz0;

        const uint2* t8 = reinterpret_cast<const uint2*>(g_hash8)
                        + (size_t)(l - NDENSE) * (TBLSZ / 4);
        const unsigned* t4 = reinterpret_cast<const unsigned*>(g_hash8)
                           + (size_t)(l - NDENSE) * (TBLSZ / 2);

        float wwy[2] = {1.0f - wy, wy};
        float wwz[2] = {1.0f - wz, wz};
        unsigned hyv[2] = {hy0, hy1};
        unsigned hzv[2] = {hz0, hz1};
        float wA = 1.0f - wx, wB = wx;
        __half2 accA = __float2half2_rn(0.0f);
        __half2 accB = __float2half2_rn(0.0f);

        #pragma unroll
        for (int yi = 0; yi < 2; yi++) {
            #pragma unroll
            for (int zi = 0; zi < 2; zi++) {
                unsigned h  = hyv[yi] ^ hzv[zi];
                unsigned iA = (h ^ x0) & HMASK;
                unsigned iB = (h ^ x1) & HMASK;
                unsigned bA = iA >> 2;
                uint2 qh = __ldg(t8 + bA);
                unsigned wordA = (iA & 2) ? qh.y : qh.x;
                unsigned short hwA = (unsigned short)(wordA >> ((iA & 1) << 4));
                unsigned wordB;
                if ((iB >> 2) == bA) {
                    wordB = (iB & 2) ? qh.y : qh.x;
                } else {
                    wordB = __ldg(t4 + (iB >> 1));   // ~25% of lanes
                }
                unsigned short hwB = (unsigned short)(wordB >> ((iB & 1) << 4));

                float wyz = wwy[yi] * wwz[zi];
                accA = __hfma2(__float2half2_rn(wyz * wA), f8unpack(hwA), accA);
                accB = __hfma2(__float2half2_rn(wyz * wB), f8unpack(hwB), accB);
            }
        }
        float2 e = __half22float2(__hadd2(accA, accB));
        ew[l & 3] = bf16x2_of(e.x, e.y);
        if ((l & 3) == 3)
            *reinterpret_cast<uint4*>(myrow + (l >> 2) * 16) =
                make_uint4(ew[0], ew[1], ew[2], ew[3]);
    }

    __syncwarp();

    // ---- A fragments: 2 M-tiles x 2 K-tiles ----
    uint32_t sab = smem_u32(s_enc) + (warp * 32) * 80;
    uint32_t swb = smem_u32(s_w1);
    uint32_t af[2][2][4];
    #pragma unroll
    for (int m = 0; m < 2; m++) {
        #pragma unroll
        for (int k = 0; k < 2; k++) {
            uint32_t addr = sab + (m * 16 + (lane & 15)) * 80 + k * 32 + ((lane >> 4) << 4);
            ldsm_x4(addr, af[m][k][0], af[m][k][1], af[m][k][2], af[m][k][3]);
        }
    }

    // ---- MMA over 16 n8-tiles, fused ReLU + layer-2 (w2 via uniform __ldg) ----
    float dacc[4] = {0, 0, 0, 0};
    float c0[4] = {0, 0, 0, 0}, c1[4] = {0, 0, 0, 0}, c2[4] = {0, 0, 0, 0};

    #pragma unroll
    for (int n = 0; n < 16; n++) {
        uint32_t b0, b1, b2, b3;
        uint32_t baddr = swb + (8 * n + (lane & 7)) * 80 + ((lane >> 3) << 4);
        ldsm_x4(baddr, b0, b1, b2, b3);

        #pragma unroll
        for (int m = 0; m < 2; m++) {
            float d0 = 0, d1 = 0, d2 = 0, d3 = 0;
            mma_bf16(d0, d1, d2, d3,
                     af[m][0][0], af[m][0][1], af[m][0][2], af[m][0][3], b0, b1);
            mma_bf16(d0, d1, d2, d3,
                     af[m][1][0], af[m][1][1], af[m][1][2], af[m][1][3], b2, b3);
            float r0 = fmaxf(d0, 0.0f), r1 = fmaxf(d1, 0.0f);
            float r2 = fmaxf(d2, 0.0f), r3 = fmaxf(d3, 0.0f);
            if (n < 8) {
                int j0 = 8 * n + 2 * q;
                float w0 = __ldg(&g_w2[j0]), w1 = __ldg(&g_w2[j0 + 1]);
                dacc[2 * m + 0] += r0 * w0 + r1 * w1;
                dacc[2 * m + 1] += r2 * w0 + r3 * w1;
            } else {
                int j0 = 8 * (n - 8) + 2 * q;
                float wa0 = __ldg(&g_w2[64 + j0]),  wa1 = __ldg(&g_w2[64 + j0 + 1]);
                float wb0 = __ldg(&g_w2[128 + j0]), wb1 = __ldg(&g_w2[128 + j0 + 1]);
                float wc0 = __ldg(&g_w2[192 + j0]), wc1 = __ldg(&g_w2[192 + j0 + 1]);
                c0[2 * m + 0] += r0 * wa0 + r1 * wa1;
                c0[2 * m + 1] += r2 * wa0 + r3 * wa1;
                c1[2 * m + 0] += r0 * wb0 + r1 * wb1;
                c1[2 * m + 1] += r2 * wb0 + r3 * wb1;
                c2[2 * m + 0] += r0 * wc0 + r1 * wc1;
                c2[2 * m + 1] += r2 * wc0 + r3 * wc1;
            }
        }
    }

    #pragma unroll
    for (int i = 0; i < 4; i++) {
        dacc[i] += __shfl_xor_sync(0xFFFFFFFF, dacc[i], 1);
        dacc[i] += __shfl_xor_sync(0xFFFFFFFF, dacc[i], 2);
        c0[i]   += __shfl_xor_sync(0xFFFFFFFF, c0[i], 1);
        c0[i]   += __shfl_xor_sync(0xFFFFFFFF, c0[i], 2);
        c1[i]   += __shfl_xor_sync(0xFFFFFFFF, c1[i], 1);
        c1[i]   += __shfl_xor_sync(0xFFFFFFFF, c1[i], 2);
        c2[i]   += __shfl_xor_sync(0xFFFFFFFF, c2[i], 1);
        c2[i]   += __shfl_xor_sync(0xFFFFFFFF, c2[i], 2);
    }

    // ---- activations + stores, split across q==0 / q==1 lanes of each quad
    // (after the bfly reduction every lane holds the sums) ----
    if (q < 2) {
        int base = blockIdx.x * 256 + warp * 32;
        #pragma unroll
        for (int i = 0; i < 4; i++) {
            int pt = base + g + 16 * (i >> 1) + 8 * (i & 1);
            if (pt < N) {
                if (q == 0) {
                    float density = fmaxf(dacc[i], 0.0f) + log1pf(expf(-fabsf(dacc[i])));
                    out[(size_t)3 * N + pt] = density;
                    out[pt * 3 + 0] = 1.0f / (1.0f + expf(-c0[i]));
                } else {
                    out[pt * 3 + 1] = 1.0f / (1.0f + expf(-c1[i]));
                    out[pt * 3 + 2] = 1.0f / (1.0f + expf(-c2[i]));
                }
            }
        }
    }
}

extern "C" void kernel_launch(void* const* d_in, const int* in_sizes, int n_in,
                              void* d_out, int out_size)
{
    const float* points = (const float*)d_in[0];
    const float* table  = (const float*)d_in[1];
    const float* dw1    = (const float*)d_in[2];
    const float* dw2    = (const float*)d_in[3];
    const float* fw1    = (const float*)d_in[4];
    const float* fw2    = (const float*)d_in[5];
    int N = in_sizes[0] / 3;

    LvlParams P;
    int cellBase = 0;
    for (int l = 0; l < NLVL; l++) {
        double sc = 16.0 * pow(1.447269237440378, (double)l) - 1.0;
        int res = (int)ceil(sc) + 1;
        P.scale[l] = (float)sc;
        P.res[l] = res;
        if (l < NDENSE) { P.denseBase[l] = cellBase; cellBase += res * res * res; }
    }

    // single merged prologue launch
    prep_all_kernel<<<(HASH_QUADS + 255) / 256, 256>>>(table, dw1, fw1, dw2, fw2, P);

    int blocks = (N + 255) / 256;
    nerf_field_kernel<<<blocks, 256>>>(points, (float*)d_out, N, P);
}

// round 17
// speedup vs baseline: 2.0760x; 1.0180x over previous
#include <cuda_runtime.h>
#include <cuda_bf16.h>
#include <cuda_fp16.h>
#include <math.h>
#include <stdint.h>

#define NLVL 16
#define NREC 6                       // record-levels 0..5 (dense 0-4 + densified hashed level 5)
#define TBLSZ (1u << 19)
#define HMASK (TBLSZ - 1u)
#define FSCALE 8192.0f
#define INV_FSCALE (1.0f / 8192.0f)
#define PY 2654435761u
#define PZ 805459861u
#define HASH_QUADS (11 * TBLSZ / 4)  // hash8 still stores levels 5..15 (level5 unused at runtime)
#define DENSE_CELLS 532784           // levels 0..4
#define R5 102
#define D5_CELLS (R5 * R5 * R5)      // 1061208

typedef unsigned long long ull;

struct LvlParams {
    float scale[NLVL];
    int   res[NLVL];
    int   recBase[NREC];
};

// W1 combined+transposed bf16 [128 hidden][32 feat], scaled 1/FSCALE
__device__ __align__(16) unsigned short g_w1tb[128 * 32];
// layer-2 weights: [0:64) dw2, [64:128) fw2 col0, [128:192) col1, [192:256) col2
__device__ __align__(16) float g_w2[256];
// fp8 (e4m3) hash table for levels 5..15 (scaled x8192)
__device__ __align__(16) unsigned short g_hash8[11 * TBLSZ];
// fp8 vertex table for level 5 (stage-1 scratch)
__device__ __align__(16) unsigned short g_vtx5[D5_CELLS];
// fp8 duplicated-corner records: levels 0..4 then level 5
__device__ __align__(16) uint4 g_dense8[DENSE_CELLS + D5_CELLS];

// ---------------- helpers ----------------
__device__ __forceinline__ uint32_t smem_u32(const void* p) {
    uint32_t a;
    asm("{ .reg .u64 t; cvta.to.shared.u64 t, %1; cvt.u32.u64 %0, t; }" : "=r"(a) : "l"(p));
    return a;
}
__device__ __forceinline__ unsigned short f8pack(float f0, float f1) {
    unsigned short r;
    asm("cvt.rn.satfinite.e4m3x2.f32 %0, %1, %2;" : "=h"(r) : "f"(f1), "f"(f0));
    return r;
}
__device__ __forceinline__ __half2 f8unpack(unsigned short u) {
    unsigned r;
    asm("cvt.rn.f16x2.e4m3x2 %0, %1;" : "=r"(r) : "h"(u));
    return *reinterpret_cast<__half2*>(&r);
}
__device__ __forceinline__ unsigned bf16x2_of(float lo, float hi) {
    unsigned r;
    asm("cvt.rn.bf16x2.f32 %0, %1, %2;" : "=r"(r) : "f"(hi), "f"(lo));
    return r;
}
__device__ __forceinline__ void ldsm_x4(uint32_t addr, uint32_t& r0, uint32_t& r1,
                                        uint32_t& r2, uint32_t& r3) {
    asm volatile("ldmatrix.sync.aligned.m8n8.x4.shared.b16 {%0,%1,%2,%3}, [%4];"
                 : "=r"(r0), "=r"(r1), "=r"(r2), "=r"(r3) : "r"(addr));
}
__device__ __forceinline__ void mma_bf16(float& d0, float& d1, float& d2, float& d3,
                                         uint32_t a0, uint32_t a1, uint32_t a2, uint32_t a3,
                                         uint32_t b0, uint32_t b1) {
    asm volatile(
        "mma.sync.aligned.m16n8k16.row.col.f32.bf16.bf16.f32 "
        "{%0,%1,%2,%3}, {%4,%5,%6,%7}, {%8,%9}, {%0,%1,%2,%3};"
        : "+f"(d0), "+f"(d1), "+f"(d2), "+f"(d3)
        : "r"(a0), "r"(a1), "r"(a2), "r"(a3), "r"(b0), "r"(b1));
}

// ---------------- prologue kernel 1: conversions + level-5 vertex gather ----------------
__global__ void prep_all_kernel(const float* __restrict__ table,
                                const float* __restrict__ dw1,
                                const float* __restrict__ fw1,
                                const float* __restrict__ dw2,
                                const float* __restrict__ fw2,
                                LvlParams P)
{
    int t = blockIdx.x * 256 + threadIdx.x;

    if (t < HASH_QUADS) {
        const float4* src = reinterpret_cast<const float4*>(table)
                          + (size_t)5 * (TBLSZ / 2) + (size_t)t * 2;
        float4 a = src[0];
        float4 b = src[1];
        uint2 o;
        o.x = (unsigned)f8pack(a.x * FSCALE, a.y * FSCALE)
            | ((unsigned)f8pack(a.z * FSCALE, a.w * FSCALE) << 16);
        o.y = (unsigned)f8pack(b.x * FSCALE, b.y * FSCALE)
            | ((unsigned)f8pack(b.z * FSCALE, b.w * FSCALE) << 16);
        reinterpret_cast<uint2*>(g_hash8)[t] = o;
    }

    // dense levels 0..4: duplicated-corner records (stride indexing)
    if (t < DENSE_CELLS) {
        int l = 0;
        #pragma unroll
        for (int k = 1; k < 5; k++)
            if (t >= P.recBase[k]) l = k;
        int cid = t - P.recBase[l];
        int R = P.res[l];
        int cx = cid % R;
        int u  = cid / R;
        int cy = u % R;
        int cz = u / R;
        const float2* tl = reinterpret_cast<const float2*>(table) + (size_t)l * TBLSZ;
        unsigned short e[8];
        #pragma unroll
        for (int c = 0; c < 8; c++) {
            int gx = min(cx + ((c >> 2) & 1), R - 1);
            int gy = min(cy + ((c >> 1) & 1), R - 1);
            int gz = min(cz + (c & 1), R - 1);
            float2 v = tl[gx + R * (gy + R * gz)];
            e[c] = f8pack(v.x * FSCALE, v.y * FSCALE);
        }
        uint4 o;
        o.x = (unsigned)e[0] | ((unsigned)e[1] << 16);
        o.y = (unsigned)e[2] | ((unsigned)e[3] << 16);
        o.z = (unsigned)e[4] | ((unsigned)e[5] << 16);
        o.w = (unsigned)e[6] | ((unsigned)e[7] << 16);
        g_dense8[t] = o;
    }

    // level-5 vertex values: ONE hash gather per vertex (stage 1)
    if (t < D5_CELLS) {
        int gx = t % R5;
        int u  = t / R5;
        int gy = u % R5;
        int gz = u / R5;
        unsigned idx = ((unsigned)gx ^ ((unsigned)gy * PY) ^ ((unsigned)gz * PZ)) & HMASK;
        const float2* tl = reinterpret_cast<const float2*>(table) + (size_t)5 * TBLSZ;
        float2 v = __ldg(tl + idx);
        g_vtx5[t] = f8pack(v.x * FSCALE, v.y * FSCALE);
    }

    if (t < 4096) {
        int j = t >> 5, k = t & 31;
        float v = (j < 64 ? dw1[k * 64 + j] : fw1[k * 64 + (j - 64)]) * INV_FSCALE;
        g_w1tb[t] = __bfloat16_as_ushort(__float2bfloat16(v));
    }

    if (t < 64) {
        g_w2[t]       = dw2[t];
        g_w2[64 + t]  = fw2[3 * t + 0];
        g_w2[128 + t] = fw2[3 * t + 1];
        g_w2[192 + t] = fw2[3 * t + 2];
    }
}

// ---------------- prologue kernel 2: level-5 record assembly (stage 2, x-coalesced) ----------------
__global__ void dense5_kernel()
{
    int t = blockIdx.x * 256 + threadIdx.x;
    if (t >= D5_CELLS) return;
    int cx = t % R5;
    int u  = t / R5;
    int cy = u % R5;
    int cz = u / R5;
    int x1 = min(cx + 1, R5 - 1);
    int y1 = min(cy + 1, R5 - 1);
    int z1 = min(cz + 1, R5 - 1);
    int b00 = cx + R5 * (cy + R5 * cz);
    int b01 = cx + R5 * (cy + R5 * z1);
    int b10 = cx + R5 * (y1 + R5 * cz);
    int b11 = cx + R5 * (y1 + R5 * z1);
    int dx = x1 - cx;
    unsigned short e0 = g_vtx5[b00], e1 = g_vtx5[b01];
    unsigned short e2 = g_vtx5[b10], e3 = g_vtx5[b11];
    unsigned short e4 = g_vtx5[b00 + dx], e5 = g_vtx5[b01 + dx];
    unsigned short e6 = g_vtx5[b10 + dx], e7 = g_vtx5[b11 + dx];
    uint4 o;
    o.x = (unsigned)e0 | ((unsigned)e1 << 16);
    o.y = (unsigned)e2 | ((unsigned)e3 << 16);
    o.z = (unsigned)e4 | ((unsigned)e5 << 16);
    o.w = (unsigned)e6 | ((unsigned)e7 << 16);
    g_dense8[DENSE_CELLS + t] = o;
}

// ---------------- main kernel ----------------
__global__ void __launch_bounds__(256, 4)
nerf_field_kernel(const float* __restrict__ points,
                  float* __restrict__ out,
                  int N, LvlParams P)
{
    __shared__ __align__(16) unsigned char s_w1[128 * 80];
    __shared__ __align__(16) unsigned char s_enc[256 * 80];

    const int tid  = threadIdx.x;
    const int lane = tid & 31;
    const int warp = tid >> 5;
    const int g = lane >> 2;
    const int q = lane & 3;

    if (tid < 128) {
        const uint4* src = reinterpret_cast<const uint4*>(g_w1tb) + tid * 4;
        uint4* dst = reinterpret_cast<uint4*>(s_w1 + tid * 80);
        dst[0] = src[0]; dst[1] = src[1]; dst[2] = src[2]; dst[3] = src[3];
    }
    __syncthreads();

    int gid = blockIdx.x * 256 + tid;
    int gc = min(gid, N - 1);

    float x = fminf(fmaxf((points[gc * 3 + 0] + 1.0f) * 0.5f, 0.0f), 1.0f);
    float y = fminf(fmaxf((points[gc * 3 + 1] + 1.0f) * 0.5f, 0.0f), 1.0f);
    float z = fminf(fmaxf((points[gc * 3 + 2] + 1.0f) * 0.5f, 0.0f), 1.0f);

    unsigned char* myrow = s_enc + tid * 80;
    unsigned ew[4];   // 4 levels buffered -> one STS.128 per group

    // ---- record levels 0..5: one 16B duplicated-corner record per cell ----
    #pragma unroll
    for (int l = 0; l < NREC; l++) {
        const float sc = P.scale[l];
        const int   R  = P.res[l];
        float px = x * sc + 0.5f, py = y * sc + 0.5f, pz = z * sc + 0.5f;
        float fx = floorf(px), fy = floorf(py), fz = floorf(pz);
        float wx = px - fx,    wy = py - fy,    wz = pz - fz;
        int cell = (int)fx + R * ((int)fy + R * (int)fz);

        uint4 qd = __ldg(&g_dense8[P.recBase[l] + cell]);

        float wx0 = 1.0f - wx, wy0 = 1.0f - wy, wz0 = 1.0f - wz;
        float w00 = wy0 * wz0, w01 = wy0 * wz, w10 = wy * wz0, w11 = wy * wz;

        __half2 a0 = __float2half2_rn(0.0f);
        __half2 a1 = __float2half2_rn(0.0f);
        a0 = __hfma2(__float2half2_rn(wx0 * w00), f8unpack((unsigned short)(qd.x      )), a0);
        a1 = __hfma2(__float2half2_rn(wx0 * w01), f8unpack((unsigned short)(qd.x >> 16)), a1);
        a0 = __hfma2(__float2half2_rn(wx0 * w10), f8unpack((unsigned short)(qd.y      )), a0);
        a1 = __hfma2(__float2half2_rn(wx0 * w11), f8unpack((unsigned short)(qd.y >> 16)), a1);
        a0 = __hfma2(__float2half2_rn(wx  * w00), f8unpack((unsigned short)(qd.z      )), a0);
        a1 = __hfma2(__float2half2_rn(wx  * w01), f8unpack((unsigned short)(qd.z >> 16)), a1);
        a0 = __hfma2(__float2half2_rn(wx  * w10), f8unpack((unsigned short)(qd.w      )), a0);
        a1 = __hfma2(__float2half2_rn(wx  * w11), f8unpack((unsigned short)(qd.w >> 16)), a1);
        float2 e = __half22float2(__hadd2(a0, a1));
        ew[l & 3] = bf16x2_of(e.x, e.y);
        if ((l & 3) == 3)
            *reinterpret_cast<uint4*>(myrow + (l >> 2) * 16) =
                make_uint4(ew[0], ew[1], ew[2], ew[3]);
    }

    // ---- hashed levels 6..15 ----
    #pragma unroll
    for (int l = NREC; l < NLVL; l++) {
        const float sc = P.scale[l];
        const int   R  = P.res[l];
        float px = x * sc + 0.5f, py = y * sc + 0.5f, pz = z * sc + 0.5f;
        float fx = floorf(px), fy = floorf(py), fz = floorf(pz);
        float wx = px - fx,    wy = py - fy,    wz = pz - fz;
        int ix = (int)fx, iy = (int)fy, iz = (int)fz;

        unsigned x0 = (unsigned)ix;
        unsigned x1 = (ix + 1 < R) ? x0 + 1u : x0;
        unsigned hy0 = (unsigned)iy * PY;
        unsigned hy1 = (iy + 1 < R) ? hy0 + PY : hy0;
        unsigned hz0 = (unsigned)iz * PZ;
        unsigned hz1 = (iz + 1 < R) ? hz0 + PZ : hz0;

        const uint2* t8 = reinterpret_cast<const uint2*>(g_hash8)
                        + (size_t)(l - 5) * (TBLSZ / 4);
        const unsigned* t4 = reinterpret_cast<const unsigned*>(g_hash8)
                           + (size_t)(l - 5) * (TBLSZ / 2);

        float wwy[2] = {1.0f - wy, wy};
        float wwz[2] = {1.0f - wz, wz};
        unsigned hyv[2] = {hy0, hy1};
        unsigned hzv[2] = {hz0, hz1};
        float wA = 1.0f - wx, wB = wx;
        __half2 accA = __float2half2_rn(0.0f);
        __half2 accB = __float2half2_rn(0.0f);

        #pragma unroll
        for (int yi = 0; yi < 2; yi++) {
            #pragma unroll
            for (int zi = 0; zi < 2; zi++) {
                unsigned h  = hyv[yi] ^ hzv[zi];
                unsigned iA = (h ^ x0) & HMASK;
                unsigned iB = (h ^ x1) & HMASK;
                unsigned bA = iA >> 2;
                uint2 qh = __ldg(t8 + bA);
                unsigned wordA = (iA & 2) ? qh.y : qh.x;
                unsigned short hwA = (unsigned short)(wordA >> ((iA & 1) << 4));
                unsigned wordB;
                if ((iB >> 2) == bA) {
                    wordB = (iB & 2) ? qh.y : qh.x;
                } else {
                    wordB = __ldg(t4 + (iB >> 1));   // ~25% of lanes
                }
                unsigned short hwB = (unsigned short)(wordB >> ((iB & 1) << 4));

                float wyz = wwy[yi] * wwz[zi];
                accA = __hfma2(__float2half2_rn(wyz * wA), f8unpack(hwA), accA);
                accB = __hfma2(__float2half2_rn(wyz * wB), f8unpack(hwB), accB);
            }
        }
        float2 e = __half22float2(__hadd2(accA, accB));
        ew[l & 3] = bf16x2_of(e.x, e.y);
        if ((l & 3) == 3)
            *reinterpret_cast<uint4*>(myrow + (l >> 2) * 16) =
                make_uint4(ew[0], ew[1], ew[2], ew[3]);
    }

    __syncwarp();

    // ---- A fragments: 2 M-tiles x 2 K-tiles ----
    uint32_t sab = smem_u32(s_enc) + (warp * 32) * 80;
    uint32_t swb = smem_u32(s_w1);
    uint32_t af[2][2][4];
    #pragma unroll
    for (int m = 0; m < 2; m++) {
        #pragma unroll
        for (int k = 0; k < 2; k++) {
            uint32_t addr = sab + (m * 16 + (lane & 15)) * 80 + k * 32 + ((lane >> 4) << 4);
            ldsm_x4(addr, af[m][k][0], af[m][k][1], af[m][k][2], af[m][k][3]);
        }
    }

    // ---- MMA over 16 n8-tiles, fused ReLU + layer-2 ----
    float dacc[4] = {0, 0, 0, 0};
    float c0[4] = {0, 0, 0, 0}, c1[4] = {0, 0, 0, 0}, c2[4] = {0, 0, 0, 0};

    #pragma unroll
    for (int n = 0; n < 16; n++) {
        uint32_t b0, b1, b2, b3;
        uint32_t baddr = swb + (8 * n + (lane & 7)) * 80 + ((lane >> 3) << 4);
        ldsm_x4(baddr, b0, b1, b2, b3);

        #pragma unroll
        for (int m = 0; m < 2; m++) {
            float d0 = 0, d1 = 0, d2 = 0, d3 = 0;
            mma_bf16(d0, d1, d2, d3,
                     af[m][0][0], af[m][0][1], af[m][0][2], af[m][0][3], b0, b1);
            mma_bf16(d0, d1, d2, d3,
                     af[m][1][0], af[m][1][1], af[m][1][2], af[m][1][3], b2, b3);
            float r0 = fmaxf(d0, 0.0f), r1 = fmaxf(d1, 0.0f);
            float r2 = fmaxf(d2, 0.0f), r3 = fmaxf(d3, 0.0f);
            if (n < 8) {
                int j0 = 8 * n + 2 * q;
                float w0 = __ldg(&g_w2[j0]), w1 = __ldg(&g_w2[j0 + 1]);
                dacc[2 * m + 0] += r0 * w0 + r1 * w1;
                dacc[2 * m + 1] += r2 * w0 + r3 * w1;
            } else {
                int j0 = 8 * (n - 8) + 2 * q;
                float wa0 = __ldg(&g_w2[64 + j0]),  wa1 = __ldg(&g_w2[64 + j0 + 1]);
                float wb0 = __ldg(&g_w2[128 + j0]), wb1 = __ldg(&g_w2[128 + j0 + 1]);
                float wc0 = __ldg(&g_w2[192 + j0]), wc1 = __ldg(&g_w2[192 + j0 + 1]);
                c0[2 * m + 0] += r0 * wa0 + r1 * wa1;
                c0[2 * m + 1] += r2 * wa0 + r3 * wa1;
                c1[2 * m + 0] += r0 * wb0 + r1 * wb1;
                c1[2 * m + 1] += r2 * wb0 + r3 * wb1;
                c2[2 * m + 0] += r0 * wc0 + r1 * wc1;
                c2[2 * m + 1] += r2 * wc0 + r3 * wc1;
            }
        }
    }

    #pragma unroll
    for (int i = 0; i < 4; i++) {
        dacc[i] += __shfl_xor_sync(0xFFFFFFFF, dacc[i], 1);
        dacc[i] += __shfl_xor_sync(0xFFFFFFFF, dacc[i], 2);
        c0[i]   += __shfl_xor_sync(0xFFFFFFFF, c0[i], 1);
        c0[i]   += __shfl_xor_sync(0xFFFFFFFF, c0[i], 2);
        c1[i]   += __shfl_xor_sync(0xFFFFFFFF, c1[i], 1);
        c1[i]   += __shfl_xor_sync(0xFFFFFFFF, c1[i], 2);
        c2[i]   += __shfl_xor_sync(0xFFFFFFFF, c2[i], 1);
        c2[i]   += __shfl_xor_sync(0xFFFFFFFF, c2[i], 2);
    }

    // stores split across q==0 / q==1 lanes of each quad
    if (q < 2) {
        int base = blockIdx.x * 256 + warp * 32;
        #pragma unroll
        for (int i = 0; i < 4; i++) {
            int pt = base + g + 16 * (i >> 1) + 8 * (i & 1);
            if (pt < N) {
                if (q == 0) {
                    float density = fmaxf(dacc[i], 0.0f) + log1pf(expf(-fabsf(dacc[i])));
                    out[(size_t)3 * N + pt] = density;
                    out[pt * 3 + 0] = 1.0f / (1.0f + expf(-c0[i]));
                } else {
                    out[pt * 3 + 1] = 1.0f / (1.0f + expf(-c1[i]));
                    out[pt * 3 + 2] = 1.0f / (1.0f + expf(-c2[i]));
                }
            }
        }
    }
}

extern "C" void kernel_launch(void* const* d_in, const int* in_sizes, int n_in,
                              void* d_out, int out_size)
{
    const float* points = (const float*)d_in[0];
    const float* table  = (const float*)d_in[1];
    const float* dw1    = (const float*)d_in[2];
    const float* dw2    = (const float*)d_in[3];
    const float* fw1    = (const float*)d_in[4];
    const float* fw2    = (const float*)d_in[5];
    int N = in_sizes[0] / 3;

    LvlParams P;
    int cellBase = 0;
    for (int l = 0; l < NLVL; l++) {
        double sc = 16.0 * pow(1.447269237440378, (double)l) - 1.0;
        int res = (int)ceil(sc) + 1;
        P.scale[l] = (float)sc;
        P.res[l] = res;
        if (l < 5) { P.recBase[l] = cellBase; cellBase += res * res * res; }
    }
    P.recBase[5] = DENSE_CELLS;   // level-5 records appended after levels 0..4

    // prologue: stage 1 (conversions + level-5 vertex gather), then stage 2 (record assembly)
    prep_all_kernel<<<(HASH_QUADS + 255) / 256, 256>>>(table, dw1, fw1, dw2, fw2, P);
    dense5_kernel<<<(D5_CELLS + 255) / 256, 256>>>();

    int blocks = (N + 255) / 256;
    nerf_field_kernel<<<blocks, 256>>>(points, (float*)d_out, N, P);
}